// round 16
// baseline (speedup 1.0000x reference)
#include <cuda_runtime.h>

#define NB    32
#define CCH   192
#define HW    112
#define IMG   (HW*HW)
#define NIMG  (CCH*NB)        // 6144 images
#define GRIDB 888             // 6 blocks/SM x 148 SMs -- ALL co-resident (see launch_bounds)
#define NHW_F ((float)(NB*IMG))
#define BN_EPS 1e-5f

// Scratch (no cudaMalloc allowed)
__device__ float g_p1[NIMG];        // per-(c,n) sum of raw conv, channel-major
__device__ float g_p2[NIMG];        // per-(c,n) sum of raw conv^2
__device__ unsigned g_bar1;         // barrier arrive counter (reset each launch)
__device__ unsigned g_bar2;         // barrier exit counter   (reset each launch)

// Load 6 input rows (h-1 .. h+4) as float4 per lane; lanes >=28 and OOB rows get 0.
__device__ __forceinline__ void load_rows(const float* __restrict__ base,
                                          int h, int lane, bool active,
                                          float4* v) {
    #pragma unroll
    for (int r = 0; r < 6; r++) {
        int row = h - 1 + r;
        float4 t = make_float4(0.f, 0.f, 0.f, 0.f);
        if (active && (unsigned)row < HW)
            t = __ldg(reinterpret_cast<const float4*>(base + row * HW) + lane);
        v[r] = t;
    }
}

// Scalar conv 4x4 micro-tile (proven fastest form).
// NOTE: lanes >= 28 produce garbage (their left halo shuffles in lane 27's real
// data) — callers MUST mask them out of any reduction/store.
__device__ __forceinline__ void conv44(const float4* v, const float* __restrict__ k,
                                       int lane, float acc[4][4]) {
    #pragma unroll
    for (int j = 0; j < 4; j++)
        #pragma unroll
        for (int i = 0; i < 4; i++)
            acc[j][i] = 0.f;

    #pragma unroll
    for (int r = 0; r < 6; r++) {
        float left  = __shfl_up_sync(0xFFFFFFFFu, v[r].w, 1);
        float right = __shfl_down_sync(0xFFFFFFFFu, v[r].x, 1);
        if (lane == 0) left = 0.f;
        float p[6] = { left, v[r].x, v[r].y, v[r].z, v[r].w, right };
        #pragma unroll
        for (int j = 0; j < 4; j++) {
            if (j >= r - 2 && j <= r) {
                const float k0 = k[3 * (r - j) + 0];
                const float k1 = k[3 * (r - j) + 1];
                const float k2 = k[3 * (r - j) + 2];
                #pragma unroll
                for (int i = 0; i < 4; i++)
                    acc[j][i] += k0 * p[i] + k1 * p[i + 1] + k2 * p[i + 2];
            }
        }
    }
}

// Persistent fused kernel: phase 1 stats over ~7 images/block -> grid barrier ->
// phase 2 output over the SAME images in REVERSE order (L1/L2-hot re-reads).
__global__ void __launch_bounds__(224, 6)
fused_kernel(const float* __restrict__ in,  const float* __restrict__ w,
             const float* __restrict__ b,   const float* __restrict__ gamma,
             const float* __restrict__ beta, float* __restrict__ out) {
    __shared__ float red1[7], red2[7];
    int lane = threadIdx.x & 31, wid = threadIdx.x >> 5;
    bool active = lane < 28;
    int bid = blockIdx.x;

    // ---------------- Phase 1: per-image conv sums ----------------
    for (int img = bid; img < NIMG; img += GRIDB) {
        int c = img >> 5, n = img & 31;
        const float* base = in + (size_t)(n * CCH + c) * IMG;
        float k[9];
        #pragma unroll
        for (int i = 0; i < 9; i++) k[i] = __ldg(w + c * 9 + i);

        float s1 = 0.f, s2 = 0.f;
        #pragma unroll
        for (int chunk = 0; chunk < 4; chunk++) {
            int h = wid * 16 + chunk * 4;
            float4 v[6];
            load_rows(base, h, lane, active, v);
            float acc[4][4];
            conv44(v, k, lane, acc);
            if (active) {   // REQUIRED: lanes 28-31 hold garbage
                #pragma unroll
                for (int j = 0; j < 4; j++)
                    #pragma unroll
                    for (int i = 0; i < 4; i++) {
                        s1 += acc[j][i];
                        s2 += acc[j][i] * acc[j][i];
                    }
            }
        }
        #pragma unroll
        for (int off = 16; off > 0; off >>= 1) {
            s1 += __shfl_down_sync(0xFFFFFFFFu, s1, off);
            s2 += __shfl_down_sync(0xFFFFFFFFu, s2, off);
        }
        if (lane == 0) { red1[wid] = s1; red2[wid] = s2; }
        __syncthreads();
        if (threadIdx.x == 0) {
            float t1 = 0.f, t2 = 0.f;
            #pragma unroll
            for (int i = 0; i < 7; i++) { t1 += red1[i]; t2 += red2[i]; }
            g_p1[img] = t1;     // img = c*32+n: channel-major
            g_p2[img] = t2;
        }
        __syncthreads();        // protect red[] reuse next iteration
    }

    // ---------------- Grid-wide barrier (all 888 blocks co-resident) ----------
    if (threadIdx.x == 0) {
        __threadfence();                       // release partials
        atomicAdd(&g_bar1, 1u);
        volatile unsigned* vb = &g_bar1;
        while (*vb < GRIDB) __nanosleep(64);
        __threadfence();                       // acquire partials
        unsigned p = atomicAdd(&g_bar2, 1u);
        if (p == GRIDB - 1u) {                 // last out: rearm for next replay
            g_bar1 = 0u; g_bar2 = 0u;
            __threadfence();
        }
    }
    __syncthreads();

    // ---------------- Phase 2: output, same images in REVERSE order ----------
    int kmax = (NIMG - 1 - bid) / GRIDB;
    for (int kk = kmax; kk >= 0; kk--) {
        int img = bid + kk * GRIDB;
        int c = img >> 5, n = img & 31;

        // Per-warp finalize for this channel (same shfl tree as before ->
        // bit-identical scale/shift in every warp).
        float p1 = g_p1[(c << 5) + lane];
        float p2 = g_p2[(c << 5) + lane];
        #pragma unroll
        for (int off = 16; off > 0; off >>= 1) {
            p1 += __shfl_down_sync(0xFFFFFFFFu, p1, off);
            p2 += __shfl_down_sync(0xFFFFFFFFu, p2, off);
        }
        float sc_ = 0.f, sh_ = 0.f;
        if (lane == 0) {
            float bias  = __ldg(b + c);
            float sum_y = p1 + NHW_F * bias;
            float ssq_y = p2 + 2.f * bias * p1 + NHW_F * bias * bias;
            float mean  = sum_y / NHW_F;
            float var   = ssq_y / NHW_F - mean * mean;
            sc_ = __ldg(gamma + c) * rsqrtf(var + BN_EPS);
            sh_ = __ldg(beta + c) + sc_ * (bias - mean);
        }
        float sc = __shfl_sync(0xFFFFFFFFu, sc_, 0);
        float sh = __shfl_sync(0xFFFFFFFFu, sh_, 0);

        const float* base = in + (size_t)(n * CCH + c) * IMG;
        float* obase = out + (size_t)(n * CCH + c) * IMG;
        float k[9];
        #pragma unroll
        for (int i = 0; i < 9; i++) k[i] = __ldg(w + c * 9 + i);

        #pragma unroll
        for (int chunk = 0; chunk < 4; chunk++) {
            int h = wid * 16 + chunk * 4;
            float4 v[6];
            load_rows(base, h, lane, active, v);
            float acc[4][4];
            conv44(v, k, lane, acc);
            if (active) {
                float* ob = obase + h * HW + lane * 4;
                #pragma unroll
                for (int j = 0; j < 4; j++) {
                    float4 o;
                    o.x = fminf(fmaxf(fmaf(acc[j][0], sc, sh), 0.f), 6.f);
                    o.y = fminf(fmaxf(fmaf(acc[j][1], sc, sh), 0.f), 6.f);
                    o.z = fminf(fmaxf(fmaf(acc[j][2], sc, sh), 0.f), 6.f);
                    o.w = fminf(fmaxf(fmaf(acc[j][3], sc, sh), 0.f), 6.f);
                    *reinterpret_cast<float4*>(ob + j * HW) = o;
                }
            }
        }
    }
}

extern "C" void kernel_launch(void* const* d_in, const int* in_sizes, int n_in,
                              void* d_out, int out_size) {
    const float* in    = (const float*)d_in[0];
    const float* w     = (const float*)d_in[1];
    const float* b     = (const float*)d_in[2];
    const float* gamma = (const float*)d_in[3];
    const float* beta  = (const float*)d_in[4];
    float* out = (float*)d_out;

    fused_kernel<<<GRIDB, 224>>>(in, w, b, gamma, beta, out);
}

// round 17
// speedup vs baseline: 1.1322x; 1.1322x over previous
#include <cuda_runtime.h>

#define NB   32
#define CCH  192
#define HW   112
#define IMG  (HW*HW)
#define TILE_H 16
#define TILES  (HW / TILE_H)   // 7
#define NHW_F  ((float)(NB*IMG))
#define BN_EPS 1e-5f

// Scratch (no cudaMalloc allowed): per-(c,n) partial sums (channel-major) + affine.
__device__ float g_p1[CCH * NB];   // sum of raw conv (no bias)
__device__ float g_p2[CCH * NB];   // sum of raw conv^2
__device__ float g_scale[CCH];
__device__ float g_shift[CCH];

// ---- bf16x2 helpers (stats pass only; output pass stays fp32-exact) ----
__device__ __forceinline__ unsigned bfpair(float lo, float hi) {
    unsigned r;  // d = {hi:bf16, lo:bf16}
    asm("cvt.rn.bf16x2.f32 %0, %1, %2;" : "=r"(r) : "f"(hi), "f"(lo));
    return r;
}
__device__ __forceinline__ unsigned hfma2(unsigned a, unsigned b, unsigned c) {
    unsigned d;
    asm("fma.rn.bf16x2 %0, %1, %2, %3;" : "=r"(d) : "r"(a), "r"(b), "r"(c));
    return d;
}
__device__ __forceinline__ float bflo(unsigned v) { return __uint_as_float(v << 16); }
__device__ __forceinline__ float bfhi(unsigned v) { return __uint_as_float(v & 0xFFFF0000u); }

// Load 6 input rows (h-1 .. h+4) as float4 per lane; lanes >=28 and OOB rows get 0.
__device__ __forceinline__ void load_rows(const float* __restrict__ base,
                                          int h, int lane, bool active,
                                          float4* v) {
    #pragma unroll
    for (int r = 0; r < 6; r++) {
        int row = h - 1 + r;
        float4 t = make_float4(0.f, 0.f, 0.f, 0.f);
        if (active && (unsigned)row < HW)
            t = __ldg(reinterpret_cast<const float4*>(base + row * HW) + lane);
        v[r] = t;
    }
}

// Scalar conv 4x4 micro-tile (proven fastest form; used by output kernel).
// NOTE: lanes >= 28 produce garbage — callers MUST mask them out.
__device__ __forceinline__ void conv44(const float4* v, const float* __restrict__ k,
                                       int lane, float acc[4][4]) {
    #pragma unroll
    for (int j = 0; j < 4; j++)
        #pragma unroll
        for (int i = 0; i < 4; i++)
            acc[j][i] = 0.f;

    #pragma unroll
    for (int r = 0; r < 6; r++) {
        float left  = __shfl_up_sync(0xFFFFFFFFu, v[r].w, 1);
        float right = __shfl_down_sync(0xFFFFFFFFu, v[r].x, 1);
        if (lane == 0) left = 0.f;
        float p[6] = { left, v[r].x, v[r].y, v[r].z, v[r].w, right };
        #pragma unroll
        for (int j = 0; j < 4; j++) {
            if (j >= r - 2 && j <= r) {
                const float k0 = k[3 * (r - j) + 0];
                const float k1 = k[3 * (r - j) + 1];
                const float k2 = k[3 * (r - j) + 2];
                #pragma unroll
                for (int i = 0; i < 4; i++)
                    acc[j][i] += k0 * p[i] + k1 * p[i + 1] + k2 * p[i + 2];
            }
        }
    }
}

// bf16x2 conv 4x4 micro-tile for STATS ONLY: accs are bf16x2 pairs
// aL[j]=(c0,c1), aH[j]=(c2,c3). Halves FMA-pipe slots (72 HFMA2 vs 144 FFMA).
__device__ __forceinline__ void conv44_bf(const float4* v, const unsigned* __restrict__ kk,
                                          int lane, unsigned aL[4], unsigned aH[4]) {
    #pragma unroll
    for (int j = 0; j < 4; j++) { aL[j] = 0u; aH[j] = 0u; }

    #pragma unroll
    for (int r = 0; r < 6; r++) {
        float left  = __shfl_up_sync(0xFFFFFFFFu, v[r].w, 1);
        float right = __shfl_down_sync(0xFFFFFFFFu, v[r].x, 1);
        if (lane == 0) left = 0.f;
        // 5 sliding bf16x2 pairs, shared by the <=3 output rows fed by row r
        unsigned q01 = bfpair(left,   v[r].x);
        unsigned q12 = bfpair(v[r].x, v[r].y);
        unsigned q23 = bfpair(v[r].y, v[r].z);
        unsigned q34 = bfpair(v[r].z, v[r].w);
        unsigned q45 = bfpair(v[r].w, right);
        #pragma unroll
        for (int j = 0; j < 4; j++) {
            if (j >= r - 2 && j <= r) {
                const unsigned k0 = kk[3 * (r - j) + 0];
                const unsigned k1 = kk[3 * (r - j) + 1];
                const unsigned k2 = kk[3 * (r - j) + 2];
                aL[j] = hfma2(k0, q01, aL[j]);
                aL[j] = hfma2(k1, q12, aL[j]);
                aL[j] = hfma2(k2, q23, aL[j]);
                aH[j] = hfma2(k0, q23, aH[j]);
                aH[j] = hfma2(k1, q34, aH[j]);
                aH[j] = hfma2(k2, q45, aH[j]);
            }
        }
    }
}

// Pass 1: per-(c,n) sums of conv and conv^2 in bf16 conv / fp32 accumulation.
// Stats-only precision loss ~1e-5 relative on mean/var — output stays fp32.
__global__ void __launch_bounds__(224)
stats_kernel(const float* __restrict__ in, const float* __restrict__ w) {
    __shared__ float red1[7], red2[7];
    int lane = threadIdx.x & 31, wid = threadIdx.x >> 5;
    int c = blockIdx.x, n = blockIdx.y;
    bool active = lane < 28;
    const float* base = in + (size_t)(n * CCH + c) * IMG;

    unsigned kk[9];
    #pragma unroll
    for (int i = 0; i < 9; i++) { float t = __ldg(w + c * 9 + i); kk[i] = bfpair(t, t); }

    float s1 = 0.f, s2 = 0.f;
    #pragma unroll
    for (int chunk = 0; chunk < 4; chunk++) {
        int h = wid * TILE_H + chunk * 4;
        float4 v[6];
        load_rows(base, h, lane, active, v);
        unsigned aL[4], aH[4];
        conv44_bf(v, kk, lane, aL, aH);
        if (active) {   // REQUIRED: lanes 28-31 hold garbage
            #pragma unroll
            for (int j = 0; j < 4; j++) {
                float y0 = bflo(aL[j]), y1 = bfhi(aL[j]);
                float y2 = bflo(aH[j]), y3 = bfhi(aH[j]);
                s1 += (y0 + y1) + (y2 + y3);
                s2 += y0 * y0 + y1 * y1 + y2 * y2 + y3 * y3;
            }
        }
    }

    #pragma unroll
    for (int off = 16; off > 0; off >>= 1) {
        s1 += __shfl_down_sync(0xFFFFFFFFu, s1, off);
        s2 += __shfl_down_sync(0xFFFFFFFFu, s2, off);
    }
    if (lane == 0) { red1[wid] = s1; red2[wid] = s2; }
    __syncthreads();
    if (threadIdx.x == 0) {
        float t1 = 0.f, t2 = 0.f;
        #pragma unroll
        for (int i = 0; i < 7; i++) { t1 += red1[i]; t2 += red2[i]; }
        g_p1[c * NB + n] = t1;      // channel-major: finalize reads coalesced
        g_p2[c * NB + n] = t2;
    }
}

// Parallel finalize (proven): one warp per channel. PDL: implicit trigger only
// (R15 showed explicit early triggers regress).
__global__ void finalize_kernel(const float* __restrict__ b,
                                const float* __restrict__ gamma,
                                const float* __restrict__ beta) {
    cudaGridDependencySynchronize();   // wait for stats partials
    int c = blockIdx.x;
    int lane = threadIdx.x;
    float p1 = g_p1[c * NB + lane];
    float p2 = g_p2[c * NB + lane];
    #pragma unroll
    for (int off = 16; off > 0; off >>= 1) {
        p1 += __shfl_down_sync(0xFFFFFFFFu, p1, off);
        p2 += __shfl_down_sync(0xFFFFFFFFu, p2, off);
    }
    if (lane == 0) {
        float bias  = __ldg(b + c);
        float sum_y = p1 + NHW_F * bias;
        float ssq_y = p2 + 2.f * bias * p1 + NHW_F * bias * bias;
        float mean  = sum_y / NHW_F;
        float var   = ssq_y / NHW_F - mean * mean;
        float sc    = __ldg(gamma + c) * rsqrtf(var + BN_EPS);
        g_scale[c] = sc;
        g_shift[c] = __ldg(beta + c) + sc * (bias - mean);
    }
}

// Pass 2 (R13-proven): conv first, PDL sync, folded scale/shift + ReLU6,
// plain float4 stores. Traversal REVERSED vs stats for L2 residue hits.
__global__ void __launch_bounds__(128)
output_kernel(const float* __restrict__ in,
              const float* __restrict__ w,
              float* __restrict__ out) {
    int lane = threadIdx.x & 31;
    int wid  = threadIdx.x >> 5;
    int c = (CCH - 1) - blockIdx.y;           // reversed
    int n = (NB  - 1) - blockIdx.z;           // reversed
    int h = ((TILES - 1) - blockIdx.x) * TILE_H + wid * 4;   // reversed tiles
    bool active = lane < 28;

    const float* base = in + (size_t)(n * CCH + c) * IMG;
    float k[9];
    #pragma unroll
    for (int i = 0; i < 9; i++) k[i] = __ldg(w + c * 9 + i);

    float4 v[6];
    load_rows(base, h, lane, active, v);

    float acc[4][4];
    conv44(v, k, lane, acc);

    cudaGridDependencySynchronize();   // finalize results ready past this point
    float sc = g_scale[c];
    float sh = g_shift[c];

    if (active) {
        float* ob = out + (size_t)(n * CCH + c) * IMG + h * HW + lane * 4;
        #pragma unroll
        for (int j = 0; j < 4; j++) {
            float4 o;
            o.x = fminf(fmaxf(fmaf(acc[j][0], sc, sh), 0.f), 6.f);
            o.y = fminf(fmaxf(fmaf(acc[j][1], sc, sh), 0.f), 6.f);
            o.z = fminf(fmaxf(fmaf(acc[j][2], sc, sh), 0.f), 6.f);
            o.w = fminf(fmaxf(fmaf(acc[j][3], sc, sh), 0.f), 6.f);
            *reinterpret_cast<float4*>(ob + j * HW) = o;
        }
    }
}

extern "C" void kernel_launch(void* const* d_in, const int* in_sizes, int n_in,
                              void* d_out, int out_size) {
    const float* in    = (const float*)d_in[0];
    const float* w     = (const float*)d_in[1];
    const float* b     = (const float*)d_in[2];
    const float* gamma = (const float*)d_in[3];
    const float* beta  = (const float*)d_in[4];
    float* out = (float*)d_out;

    dim3 sgrid(CCH, NB);            // 6144 blocks, 224 threads
    stats_kernel<<<sgrid, 224>>>(in, w);

    // PDL: overlap successor launches with predecessor drain (implicit trigger).
    cudaLaunchAttribute attrs[1];
    attrs[0].id = cudaLaunchAttributeProgrammaticStreamSerialization;
    attrs[0].val.programmaticStreamSerializationAllowed = 1;

    cudaLaunchConfig_t cfgF = {};
    cfgF.gridDim = dim3(CCH);       // 192 blocks, 1 warp each
    cfgF.blockDim = dim3(32);
    cfgF.attrs = attrs;
    cfgF.numAttrs = 1;
    cfgF.stream = 0;
    cudaLaunchKernelEx(&cfgF, finalize_kernel, b, gamma, beta);

    cudaLaunchConfig_t cfgO = {};
    cfgO.gridDim = dim3(TILES, CCH, NB);   // 43008 blocks
    cfgO.blockDim = dim3(128);
    cfgO.attrs = attrs;
    cfgO.numAttrs = 1;
    cfgO.stream = 0;
    cudaLaunchKernelEx(&cfgO, output_kernel, in, w, out);
}